// round 3
// baseline (speedup 1.0000x reference)
#include <cuda_runtime.h>
#include <math.h>

#define NM 64
#define NA 24
#define NP 276
#define NPPAD 288
#define NT 6000
#define NTPAD 6016
#define QV 0.22360679774997896f   // sqrt(5)/sig
#define KE 0.016666666666666666f  // 5/(3*sig^2)

#define G1_BLOCKS 94              // 6016/64 t-tiles
#define G1_KT 18                  // 288/16 k-tiles
#define G2_PT 5                   // p-tiles of 64 (276 -> 320)
#define G2_KS 29                  // K splits over T
#define G2_CHUNK 208              // 13 k-tiles of 16
#define G2_NKT 13
#define G2_PPAD 320

typedef unsigned long long u64;

// ---------------- static device scratch ----------------
__device__ float g_qxs[NM * NP];
__device__ float g_xs3[NM * NP];
__device__ float g_nq[NM];
__device__ float g_qxsT[NPPAD * NM];
__device__ float g_nt[NTPAD];
__device__ float g_ct[NTPAD];
__device__ float g_a[NM * NTPAD];
__device__ float g_b[NM * NTPAD];
__device__ float g_Ep[G1_BLOCKS * NM];
__device__ float g_sa[G1_BLOCKS * NM];
__device__ float g_F2[G2_KS * NM * G2_PPAD];

__device__ __forceinline__ void ffma2(u64& c, u64 a, u64 b) {
    asm("fma.rn.f32x2 %0, %1, %2, %0;" : "+l"(c) : "l"(a), "l"(b));
}
__device__ __forceinline__ float2 upk(u64 v) {
    float2 f;
    asm("mov.b64 {%0, %1}, %2;" : "=f"(f.x), "=f"(f.y) : "l"(v));
    return f;
}

__device__ __forceinline__ void pair_ij(int p, int& i, int& j) {
    int ii = (int)((1.0f + sqrtf(1.0f + 8.0f * (float)p)) * 0.5f);
    while (ii * (ii - 1) / 2 > p) ii--;
    while ((ii + 1) * ii / 2 <= p) ii++;
    i = ii;
    j = p - ii * (ii - 1) / 2;
}

// ---------------- prep1 ----------------
__global__ void prep1_kernel(const float* __restrict__ Rs) {
    __shared__ float red[288];
    int m = blockIdx.x;
    int p = threadIdx.x;
    float qv = 0.0f;
    if (p < NP) {
        int i, j;
        pair_ij(p, i, j);
        float dx = Rs[(m * NA + i) * 3 + 0] - Rs[(m * NA + j) * 3 + 0];
        float dy = Rs[(m * NA + i) * 3 + 1] - Rs[(m * NA + j) * 3 + 1];
        float dz = Rs[(m * NA + i) * 3 + 2] - Rs[(m * NA + j) * 3 + 2];
        float d = sqrtf(dx * dx + dy * dy + dz * dz);
        float xs = 1.0f / d;
        g_qxs[m * NP + p] = QV * xs;
        g_xs3[m * NP + p] = xs * xs * xs;
        qv = QV * xs;
    }
    g_qxsT[p * NM + m] = qv;
    red[p] = qv * qv;
    __syncthreads();
    if (p < 32) {
        float s = red[p];
        for (int k = p + 32; k < 288; k += 32) s += red[k];
        #pragma unroll
        for (int o = 16; o > 0; o >>= 1) s += __shfl_xor_sync(0xffffffffu, s, o);
        if (p == 0) g_nq[m] = s;
    }
}

// ---------------- prep2 ----------------
__global__ void prep2_kernel(const float* __restrict__ xt, const float* __restrict__ jx) {
    int w = (blockIdx.x * blockDim.x + threadIdx.x) >> 5;
    int lane = threadIdx.x & 31;
    if (w >= NTPAD) return;
    if (w >= NT) {
        if (lane == 0) { g_nt[w] = 0.0f; g_ct[w] = 0.0f; }
        return;
    }
    const float* xr = xt + (size_t)w * NP;
    const float* jr = jx + (size_t)w * NP;
    float sn = 0.0f, sc = 0.0f;
    #pragma unroll
    for (int k = 0; k < 9; k++) {
        int p = lane + 32 * k;
        if (p < NP) {
            float x = xr[p];
            sn = fmaf(x, x, sn);
            sc = fmaf(x, jr[p], sc);
        }
    }
    #pragma unroll
    for (int o = 16; o > 0; o >>= 1) {
        sn += __shfl_xor_sync(0xffffffffu, sn, o);
        sc += __shfl_xor_sync(0xffffffffu, sc, o);
    }
    if (lane == 0) {
        g_nt[w] = QV * QV * sn;
        g_ct[w] = QV * sc;
    }
}

// ---------------- GEMM1 (pipelined): S1/S2 = qxs @ [xst; Jx]^T + fused epilogue ----------------
__global__ __launch_bounds__(256)
void gemm1_kernel(const float* __restrict__ xt, const float* __restrict__ jx) {
    __shared__ float As[2][16 * 128];
    __shared__ float Bx[2][16 * 68];
    __shared__ float Bj[2][16 * 68];

    const int tid = threadIdx.x;
    const int tx = tid & 15;
    const int ty = tid >> 4;
    const int t0 = blockIdx.x * 64;

    const int lak = tid >> 4, lam = tid & 15;
    const int lbt = tid >> 2, lbc = tid & 3;

    u64 acc1[4][2], acc2[4][2];
    #pragma unroll
    for (int i = 0; i < 4; i++) { acc1[i][0] = 0ull; acc1[i][1] = 0ull; acc2[i][0] = 0ull; acc2[i][1] = 0ull; }

    float4 av, xv, jv;

    // --- loaders ---
    auto ldg_tile = [&](int kt) {
        int k0 = kt * 16;
        av = *(const float4*)&g_qxsT[(k0 + lak) * NM + 4 * lam];
        int kk = k0 + 4 * lbc;
        int tg = t0 + lbt;
        xv = make_float4(0.f, 0.f, 0.f, 0.f);
        jv = make_float4(0.f, 0.f, 0.f, 0.f);
        if (tg < NT && kk < NP) {
            xv = *(const float4*)&xt[(size_t)tg * NP + kk];
            jv = *(const float4*)&jx[(size_t)tg * NP + kk];
        }
    };
    auto sts_tile = [&](int buf) {
        *(float4*)&As[buf][lak * 128 + 8 * lam]     = make_float4(av.x, av.x, av.y, av.y);
        *(float4*)&As[buf][lak * 128 + 8 * lam + 4] = make_float4(av.z, av.z, av.w, av.w);
        Bx[buf][(4 * lbc + 0) * 68 + lbt] = xv.x;
        Bx[buf][(4 * lbc + 1) * 68 + lbt] = xv.y;
        Bx[buf][(4 * lbc + 2) * 68 + lbt] = xv.z;
        Bx[buf][(4 * lbc + 3) * 68 + lbt] = xv.w;
        Bj[buf][(4 * lbc + 0) * 68 + lbt] = jv.x;
        Bj[buf][(4 * lbc + 1) * 68 + lbt] = jv.y;
        Bj[buf][(4 * lbc + 2) * 68 + lbt] = jv.z;
        Bj[buf][(4 * lbc + 3) * 68 + lbt] = jv.w;
    };

    // prologue: tile0 -> smem[0], tile1 -> regs
    ldg_tile(0);
    sts_tile(0);
    ldg_tile(1);
    __syncthreads();

    for (int kt = 0; kt < G1_KT; kt++) {
        const int cur = kt & 1;
        if (kt + 1 < G1_KT) {
            sts_tile(cur ^ 1);                 // regs hold tile kt+1
            if (kt + 2 < G1_KT) ldg_tile(kt + 2);
        }
        #pragma unroll
        for (int k = 0; k < 16; k++) {
            ulonglong2 A01 = *(const ulonglong2*)&As[cur][k * 128 + 8 * ty];
            ulonglong2 A23 = *(const ulonglong2*)&As[cur][k * 128 + 8 * ty + 4];
            ulonglong2 X  = *(const ulonglong2*)&Bx[cur][k * 68 + 4 * tx];
            ulonglong2 J  = *(const ulonglong2*)&Bj[cur][k * 68 + 4 * tx];
            ffma2(acc1[0][0], A01.x, X.x); ffma2(acc1[0][1], A01.x, X.y);
            ffma2(acc1[1][0], A01.y, X.x); ffma2(acc1[1][1], A01.y, X.y);
            ffma2(acc1[2][0], A23.x, X.x); ffma2(acc1[2][1], A23.x, X.y);
            ffma2(acc1[3][0], A23.y, X.x); ffma2(acc1[3][1], A23.y, X.y);
            ffma2(acc2[0][0], A01.x, J.x); ffma2(acc2[0][1], A01.x, J.y);
            ffma2(acc2[1][0], A01.y, J.x); ffma2(acc2[1][1], A01.y, J.y);
            ffma2(acc2[2][0], A23.x, J.x); ffma2(acc2[2][1], A23.x, J.y);
            ffma2(acc2[3][0], A23.y, J.x); ffma2(acc2[3][1], A23.y, J.y);
        }
        __syncthreads();
    }

    // fused epilogue
    const int m0 = ty * 4;
    const int tb = t0 + 4 * tx;
    float ntv[4], ctv[4];
    #pragma unroll
    for (int i = 0; i < 4; i++) { ntv[i] = g_nt[tb + i]; ctv[i] = g_ct[tb + i]; }

    float eloc[4], saloc[4];
    #pragma unroll
    for (int mi = 0; mi < 4; mi++) {
        float nqv = g_nq[m0 + mi];
        float s1v[4], s2v[4];
        float2 u;
        u = upk(acc1[mi][0]); s1v[0] = u.x; s1v[1] = u.y;
        u = upk(acc1[mi][1]); s1v[2] = u.x; s1v[3] = u.y;
        u = upk(acc2[mi][0]); s2v[0] = u.x; s2v[1] = u.y;
        u = upk(acc2[mi][1]); s2v[2] = u.x; s2v[3] = u.y;
        float oa[4], ob[4];
        float el = 0.0f, sl = 0.0f;
        #pragma unroll
        for (int j = 0; j < 4; j++) {
            float sq = fmaf(-2.0f * QV, s1v[j], nqv + ntv[j]);
            float xd = sqrtf(fmaxf(sq, 0.0f));
            float e  = KE * __expf(-xd);
            float dt = s2v[j] - ctv[j];
            float a  = e * dt;
            float b  = fmaf(e, xd, e);
            oa[j] = QV * a;
            ob[j] = b;
            el = fmaf(b, dt, el);
            sl += a;
        }
        eloc[mi] = el; saloc[mi] = sl;
        *(float4*)&g_a[(m0 + mi) * NTPAD + tb] = make_float4(oa[0], oa[1], oa[2], oa[3]);
        *(float4*)&g_b[(m0 + mi) * NTPAD + tb] = make_float4(ob[0], ob[1], ob[2], ob[3]);
    }

    __syncthreads();
    float* Es = &As[0][0];
    float* Ss = &As[0][0] + 1024;
    #pragma unroll
    for (int mi = 0; mi < 4; mi++) {
        Es[(m0 + mi) * 16 + tx] = eloc[mi];
        Ss[(m0 + mi) * 16 + tx] = saloc[mi];
    }
    __syncthreads();
    if (tid < 64) {
        float se = 0.0f, ss = 0.0f;
        #pragma unroll
        for (int x = 0; x < 16; x++) { se += Es[tid * 16 + x]; ss += Ss[tid * 16 + x]; }
        g_Ep[blockIdx.x * NM + tid] = se;
        g_sa[blockIdx.x * NM + tid] = ss;
    }
}

// ---------------- GEMM2 (pipelined): F2 = -((q a) @ xst + b @ Jx), K-split ----------------
__global__ __launch_bounds__(256)
void gemm2_kernel(const float* __restrict__ xt, const float* __restrict__ jx) {
    __shared__ float Aa[2][16 * 128];
    __shared__ float Ab[2][16 * 128];
    __shared__ float Bx[2][16 * 64];
    __shared__ float Bj[2][16 * 64];

    const int tid = threadIdx.x;
    const int tx = tid & 15;
    const int ty = tid >> 4;
    const int p0 = blockIdx.x * 64;
    const int t0 = blockIdx.y * G2_CHUNK;

    const int lam = tid >> 2, lac = tid & 3;
    const int lbk = tid >> 4, lbc = tid & 15;

    u64 acc[4][2];
    #pragma unroll
    for (int i = 0; i < 4; i++) { acc[i][0] = 0ull; acc[i][1] = 0ull; }

    float4 av, bv, xv, jv;

    auto ldg_tile = [&](int kt) {
        int tt0 = t0 + kt * 16;
        int ta = tt0 + 4 * lac;
        av = make_float4(0.f, 0.f, 0.f, 0.f);
        bv = make_float4(0.f, 0.f, 0.f, 0.f);
        if (ta < NT) {
            av = *(const float4*)&g_a[lam * NTPAD + ta];
            bv = *(const float4*)&g_b[lam * NTPAD + ta];
        }
        int tg = tt0 + lbk;
        int pc = p0 + 4 * lbc;
        xv = make_float4(0.f, 0.f, 0.f, 0.f);
        jv = make_float4(0.f, 0.f, 0.f, 0.f);
        if (tg < NT && pc < NP) {
            xv = *(const float4*)&xt[(size_t)tg * NP + pc];
            jv = *(const float4*)&jx[(size_t)tg * NP + pc];
        }
    };
    auto sts_tile = [&](int buf) {
        #pragma unroll
        for (int i = 0; i < 4; i++) {
            float va = (i == 0) ? av.x : (i == 1) ? av.y : (i == 2) ? av.z : av.w;
            float vb = (i == 0) ? bv.x : (i == 1) ? bv.y : (i == 2) ? bv.z : bv.w;
            *(float2*)&Aa[buf][(4 * lac + i) * 128 + 2 * lam] = make_float2(va, va);
            *(float2*)&Ab[buf][(4 * lac + i) * 128 + 2 * lam] = make_float2(vb, vb);
        }
        *(float4*)&Bx[buf][lbk * 64 + 4 * lbc] = xv;
        *(float4*)&Bj[buf][lbk * 64 + 4 * lbc] = jv;
    };

    ldg_tile(0);
    sts_tile(0);
    ldg_tile(1);
    __syncthreads();

    for (int kt = 0; kt < G2_NKT; kt++) {
        const int cur = kt & 1;
        if (kt + 1 < G2_NKT) {
            sts_tile(cur ^ 1);
            if (kt + 2 < G2_NKT) ldg_tile(kt + 2);
        }
        #pragma unroll
        for (int k = 0; k < 16; k++) {
            ulonglong2 Aa01 = *(const ulonglong2*)&Aa[cur][k * 128 + 8 * ty];
            ulonglong2 Aa23 = *(const ulonglong2*)&Aa[cur][k * 128 + 8 * ty + 4];
            ulonglong2 Ab01 = *(const ulonglong2*)&Ab[cur][k * 128 + 8 * ty];
            ulonglong2 Ab23 = *(const ulonglong2*)&Ab[cur][k * 128 + 8 * ty + 4];
            ulonglong2 X   = *(const ulonglong2*)&Bx[cur][k * 64 + 4 * tx];
            ulonglong2 J   = *(const ulonglong2*)&Bj[cur][k * 64 + 4 * tx];
            ffma2(acc[0][0], Aa01.x, X.x); ffma2(acc[0][1], Aa01.x, X.y);
            ffma2(acc[1][0], Aa01.y, X.x); ffma2(acc[1][1], Aa01.y, X.y);
            ffma2(acc[2][0], Aa23.x, X.x); ffma2(acc[2][1], Aa23.x, X.y);
            ffma2(acc[3][0], Aa23.y, X.x); ffma2(acc[3][1], Aa23.y, X.y);
            ffma2(acc[0][0], Ab01.x, J.x); ffma2(acc[0][1], Ab01.x, J.y);
            ffma2(acc[1][0], Ab01.y, J.x); ffma2(acc[1][1], Ab01.y, J.y);
            ffma2(acc[2][0], Ab23.x, J.x); ffma2(acc[2][1], Ab23.x, J.y);
            ffma2(acc[3][0], Ab23.y, J.x); ffma2(acc[3][1], Ab23.y, J.y);
        }
        __syncthreads();
    }

    #pragma unroll
    for (int mi = 0; mi < 4; mi++) {
        float2 u0 = upk(acc[mi][0]);
        float2 u1 = upk(acc[mi][1]);
        int m = ty * 4 + mi;
        *(float4*)&g_F2[((size_t)blockIdx.y * NM + m) * G2_PPAD + p0 + 4 * tx] =
            make_float4(-u0.x, -u0.y, -u1.x, -u1.y);
    }
}

// ---------------- final ----------------
__global__ void final_kernel(const float* __restrict__ Rs, float* __restrict__ out) {
    __shared__ float Fxs[NP];
    __shared__ float ssa;
    const int m = blockIdx.x;
    const int tid = threadIdx.x;

    if (tid < 32) {
        // parallel sa reduction
        float s = 0.0f;
        for (int b = tid; b < G1_BLOCKS; b += 32) s += g_sa[b * NM + m];
        #pragma unroll
        for (int o = 16; o > 0; o >>= 1) s += __shfl_xor_sync(0xffffffffu, s, o);
        if (tid == 0) ssa = s;
    } else if (tid < 64) {
        int l = tid - 32;
        float e = 0.0f;
        for (int b = l; b < G1_BLOCKS; b += 32) e += g_Ep[b * NM + m];
        #pragma unroll
        for (int o = 16; o > 0; o >>= 1) e += __shfl_xor_sync(0xffffffffu, e, o);
        if (l == 0) out[m] = e / QV;
    }
    __syncthreads();

    if (tid < NP) {
        float F = ssa * g_qxs[m * NP + tid];
        #pragma unroll 4
        for (int ks = 0; ks < G2_KS; ks++)
            F += g_F2[((size_t)ks * NM + m) * G2_PPAD + tid];
        Fxs[tid] = F * g_xs3[m * NP + tid];
    }
    __syncthreads();

    if (tid < NA * 3) {
        int a = tid / 3, c = tid % 3;
        float Ra = Rs[(m * NA + a) * 3 + c];
        float acc = 0.0f;
        #pragma unroll
        for (int bb = 0; bb < NA; bb++) {
            if (bb == a) continue;
            int hi = (a > bb) ? a : bb;
            int lo = (a > bb) ? bb : a;
            int p = hi * (hi - 1) / 2 + lo;
            float Rb = Rs[(m * NA + bb) * 3 + c];
            acc += (Rb - Ra) * Fxs[p];
        }
        out[NM + m * NA * 3 + tid] = acc;
    }
}

extern "C" void kernel_launch(void* const* d_in, const int* in_sizes, int n_in,
                              void* d_out, int out_size) {
    const float* Rs = (const float*)d_in[0];
    const float* xs_train = (const float*)d_in[1];
    const float* Jx = (const float*)d_in[2];
    float* out = (float*)d_out;

    prep1_kernel<<<NM, 288>>>(Rs);
    prep2_kernel<<<NTPAD / 8, 256>>>(xs_train, Jx);
    gemm1_kernel<<<G1_BLOCKS, 256>>>(xs_train, Jx);
    gemm2_kernel<<<dim3(G2_PT, G2_KS), 256>>>(xs_train, Jx);
    final_kernel<<<NM, 288>>>(Rs, out);
}

// round 4
// speedup vs baseline: 1.0319x; 1.0319x over previous
#include <cuda_runtime.h>
#include <math.h>

#define NM 64
#define NA 24
#define NP 276
#define NPPAD 288
#define NT 6000
#define NTPAD 6016
#define QV 0.22360679774997896f   // sqrt(5)/sig
#define KE 0.016666666666666666f  // 5/(3*sig^2)

#define G1_TT 94                  // t-tiles of 64
#define G1_KS 4                   // k splits of gemm1 (18 tiles total)
#define G2_PT 5                   // p-tiles of 64 (276 -> 320)
#define G2_KS 54                  // K splits over T
#define G2_CHUNK 112              // 7 k-tiles of 16
#define G2_NKT 7
#define G2_PPAD 320

typedef unsigned long long u64;

// ---------------- static device scratch ----------------
__device__ float g_qxs[NM * NP];
__device__ float g_xs3[NM * NP];
__device__ float g_nq[NM];
__device__ float g_qxsT[NPPAD * NM];
__device__ float g_nt[NTPAD];
__device__ float g_ct[NTPAD];
__device__ float g_S1p[G1_KS * NM * NTPAD];   // gemm1 partial S1
__device__ float g_S2p[G1_KS * NM * NTPAD];   // gemm1 partial S2
__device__ float g_a[NM * NTPAD];
__device__ float g_b[NM * NTPAD];
__device__ float g_Ep[G1_TT * NM];
__device__ float g_sa[G1_TT * NM];
__device__ float g_F2[G2_KS * NM * G2_PPAD];

__device__ __forceinline__ void ffma2(u64& c, u64 a, u64 b) {
    asm("fma.rn.f32x2 %0, %1, %2, %0;" : "+l"(c) : "l"(a), "l"(b));
}
__device__ __forceinline__ float2 upk(u64 v) {
    float2 f;
    asm("mov.b64 {%0, %1}, %2;" : "=f"(f.x), "=f"(f.y) : "l"(v));
    return f;
}

__device__ __forceinline__ void pair_ij(int p, int& i, int& j) {
    int ii = (int)((1.0f + sqrtf(1.0f + 8.0f * (float)p)) * 0.5f);
    while (ii * (ii - 1) / 2 > p) ii--;
    while ((ii + 1) * ii / 2 <= p) ii++;
    i = ii;
    j = p - ii * (ii - 1) / 2;
}

// ---------------- fused prep: blocks 0..63 -> descriptors; 64..815 -> t scalars ----------------
__global__ void prep_kernel(const float* __restrict__ Rs,
                            const float* __restrict__ xt,
                            const float* __restrict__ jx) {
    const int tid = threadIdx.x;
    if (blockIdx.x < NM) {
        __shared__ float red[256];
        const int m = blockIdx.x;
        float ssum = 0.0f;
        #pragma unroll
        for (int rep = 0; rep < 2; rep++) {
            int p = tid + 256 * rep;
            if (p < NP) {
                int i, j;
                pair_ij(p, i, j);
                float dx = Rs[(m * NA + i) * 3 + 0] - Rs[(m * NA + j) * 3 + 0];
                float dy = Rs[(m * NA + i) * 3 + 1] - Rs[(m * NA + j) * 3 + 1];
                float dz = Rs[(m * NA + i) * 3 + 2] - Rs[(m * NA + j) * 3 + 2];
                float d = sqrtf(dx * dx + dy * dy + dz * dz);
                float xs = 1.0f / d;
                float qv = QV * xs;
                g_qxs[m * NP + p] = qv;
                g_xs3[m * NP + p] = xs * xs * xs;
                g_qxsT[p * NM + m] = qv;
                ssum += qv * qv;
            } else if (p < NPPAD) {
                g_qxsT[p * NM + m] = 0.0f;
            }
        }
        red[tid] = ssum;
        __syncthreads();
        if (tid < 32) {
            float s = red[tid];
            #pragma unroll
            for (int k = 1; k < 8; k++) s += red[tid + 32 * k];
            #pragma unroll
            for (int o = 16; o > 0; o >>= 1) s += __shfl_xor_sync(0xffffffffu, s, o);
            if (tid == 0) g_nq[m] = s;
        }
        return;
    }
    // t-scalar part: one warp per training row
    int w = ((blockIdx.x - NM) * blockDim.x + tid) >> 5;
    int lane = tid & 31;
    if (w >= NTPAD) return;
    if (w >= NT) {
        if (lane == 0) { g_nt[w] = 0.0f; g_ct[w] = 0.0f; }
        return;
    }
    const float* xr = xt + (size_t)w * NP;
    const float* jr = jx + (size_t)w * NP;
    float sn = 0.0f, sc = 0.0f;
    #pragma unroll
    for (int k = 0; k < 9; k++) {
        int p = lane + 32 * k;
        if (p < NP) {
            float x = xr[p];
            sn = fmaf(x, x, sn);
            sc = fmaf(x, jr[p], sc);
        }
    }
    #pragma unroll
    for (int o = 16; o > 0; o >>= 1) {
        sn += __shfl_xor_sync(0xffffffffu, sn, o);
        sc += __shfl_xor_sync(0xffffffffu, sc, o);
    }
    if (lane == 0) {
        g_nt[w] = QV * QV * sn;
        g_ct[w] = QV * sc;
    }
}

// ---------------- GEMM1 partial (k-split, pipelined): S1/S2 partial sums ----------------
__global__ __launch_bounds__(256)
void gemm1p_kernel(const float* __restrict__ xt, const float* __restrict__ jx) {
    __shared__ float As[2][16 * 128];
    __shared__ float Bx[2][16 * 68];
    __shared__ float Bj[2][16 * 68];

    const int tid = threadIdx.x;
    const int tx = tid & 15;
    const int ty = tid >> 4;
    const int t0 = blockIdx.x * 64;
    const int ks = blockIdx.y;
    const int kt0 = (ks * 18) / G1_KS;
    const int kt1 = ((ks + 1) * 18) / G1_KS;

    const int lak = tid >> 4, lam = tid & 15;
    const int lbt = tid >> 2, lbc = tid & 3;

    u64 acc1[4][2], acc2[4][2];
    #pragma unroll
    for (int i = 0; i < 4; i++) { acc1[i][0] = 0ull; acc1[i][1] = 0ull; acc2[i][0] = 0ull; acc2[i][1] = 0ull; }

    float4 av, xv, jv;

    auto ldg_tile = [&](int kt) {
        int k0 = kt * 16;
        av = *(const float4*)&g_qxsT[(k0 + lak) * NM + 4 * lam];
        int kk = k0 + 4 * lbc;
        int tg = t0 + lbt;
        xv = make_float4(0.f, 0.f, 0.f, 0.f);
        jv = make_float4(0.f, 0.f, 0.f, 0.f);
        if (tg < NT && kk < NP) {
            xv = *(const float4*)&xt[(size_t)tg * NP + kk];
            jv = *(const float4*)&jx[(size_t)tg * NP + kk];
        }
    };
    auto sts_tile = [&](int buf) {
        *(float4*)&As[buf][lak * 128 + 8 * lam]     = make_float4(av.x, av.x, av.y, av.y);
        *(float4*)&As[buf][lak * 128 + 8 * lam + 4] = make_float4(av.z, av.z, av.w, av.w);
        Bx[buf][(4 * lbc + 0) * 68 + lbt] = xv.x;
        Bx[buf][(4 * lbc + 1) * 68 + lbt] = xv.y;
        Bx[buf][(4 * lbc + 2) * 68 + lbt] = xv.z;
        Bx[buf][(4 * lbc + 3) * 68 + lbt] = xv.w;
        Bj[buf][(4 * lbc + 0) * 68 + lbt] = jv.x;
        Bj[buf][(4 * lbc + 1) * 68 + lbt] = jv.y;
        Bj[buf][(4 * lbc + 2) * 68 + lbt] = jv.z;
        Bj[buf][(4 * lbc + 3) * 68 + lbt] = jv.w;
    };

    ldg_tile(kt0);
    sts_tile(0);
    if (kt0 + 1 < kt1) ldg_tile(kt0 + 1);
    __syncthreads();

    for (int kt = kt0; kt < kt1; kt++) {
        const int cur = (kt - kt0) & 1;
        if (kt + 1 < kt1) {
            sts_tile(cur ^ 1);
            if (kt + 2 < kt1) ldg_tile(kt + 2);
        }
        #pragma unroll
        for (int k = 0; k < 16; k++) {
            ulonglong2 A01 = *(const ulonglong2*)&As[cur][k * 128 + 8 * ty];
            ulonglong2 A23 = *(const ulonglong2*)&As[cur][k * 128 + 8 * ty + 4];
            ulonglong2 X  = *(const ulonglong2*)&Bx[cur][k * 68 + 4 * tx];
            ulonglong2 J  = *(const ulonglong2*)&Bj[cur][k * 68 + 4 * tx];
            ffma2(acc1[0][0], A01.x, X.x); ffma2(acc1[0][1], A01.x, X.y);
            ffma2(acc1[1][0], A01.y, X.x); ffma2(acc1[1][1], A01.y, X.y);
            ffma2(acc1[2][0], A23.x, X.x); ffma2(acc1[2][1], A23.x, X.y);
            ffma2(acc1[3][0], A23.y, X.x); ffma2(acc1[3][1], A23.y, X.y);
            ffma2(acc2[0][0], A01.x, J.x); ffma2(acc2[0][1], A01.x, J.y);
            ffma2(acc2[1][0], A01.y, J.x); ffma2(acc2[1][1], A01.y, J.y);
            ffma2(acc2[2][0], A23.x, J.x); ffma2(acc2[2][1], A23.x, J.y);
            ffma2(acc2[3][0], A23.y, J.x); ffma2(acc2[3][1], A23.y, J.y);
        }
        __syncthreads();
    }

    const int m0 = ty * 4;
    const int tb = t0 + 4 * tx;
    #pragma unroll
    for (int mi = 0; mi < 4; mi++) {
        float2 a0 = upk(acc1[mi][0]);
        float2 a1 = upk(acc1[mi][1]);
        float2 b0 = upk(acc2[mi][0]);
        float2 b1 = upk(acc2[mi][1]);
        size_t off = ((size_t)ks * NM + (m0 + mi)) * NTPAD + tb;
        *(float4*)&g_S1p[off] = make_float4(a0.x, a0.y, a1.x, a1.y);
        *(float4*)&g_S2p[off] = make_float4(b0.x, b0.y, b1.x, b1.y);
    }
}

// ---------------- epilogue: combine S partials, transcendentals, a/b/E/sa ----------------
__global__ __launch_bounds__(256)
void ep_kernel() {
    __shared__ float red[2048];
    const int tid = threadIdx.x;
    const int tx = tid & 15;
    const int ty = tid >> 4;
    const int t0 = blockIdx.x * 64;
    const int m0 = ty * 4;
    const int tb = t0 + 4 * tx;

    float ntv[4], ctv[4];
    #pragma unroll
    for (int i = 0; i < 4; i++) { ntv[i] = g_nt[tb + i]; ctv[i] = g_ct[tb + i]; }

    float eloc[4], saloc[4];
    #pragma unroll
    for (int mi = 0; mi < 4; mi++) {
        float nqv = g_nq[m0 + mi];
        float4 s1 = make_float4(0.f, 0.f, 0.f, 0.f);
        float4 s2 = make_float4(0.f, 0.f, 0.f, 0.f);
        #pragma unroll
        for (int ks = 0; ks < G1_KS; ks++) {
            size_t off = ((size_t)ks * NM + (m0 + mi)) * NTPAD + tb;
            float4 u = *(const float4*)&g_S1p[off];
            float4 v = *(const float4*)&g_S2p[off];
            s1.x += u.x; s1.y += u.y; s1.z += u.z; s1.w += u.w;
            s2.x += v.x; s2.y += v.y; s2.z += v.z; s2.w += v.w;
        }
        float s1v[4] = {s1.x, s1.y, s1.z, s1.w};
        float s2v[4] = {s2.x, s2.y, s2.z, s2.w};
        float oa[4], ob[4];
        float el = 0.0f, sl = 0.0f;
        #pragma unroll
        for (int j = 0; j < 4; j++) {
            float sq = fmaf(-2.0f * QV, s1v[j], nqv + ntv[j]);
            float xd = sqrtf(fmaxf(sq, 0.0f));
            float e  = KE * __expf(-xd);
            float dt = s2v[j] - ctv[j];
            float a  = e * dt;
            float b  = fmaf(e, xd, e);
            oa[j] = QV * a;
            ob[j] = b;
            el = fmaf(b, dt, el);
            sl += a;
        }
        eloc[mi] = el; saloc[mi] = sl;
        *(float4*)&g_a[(m0 + mi) * NTPAD + tb] = make_float4(oa[0], oa[1], oa[2], oa[3]);
        *(float4*)&g_b[(m0 + mi) * NTPAD + tb] = make_float4(ob[0], ob[1], ob[2], ob[3]);
    }

    float* Es = red;
    float* Ss = red + 1024;
    #pragma unroll
    for (int mi = 0; mi < 4; mi++) {
        Es[(m0 + mi) * 16 + tx] = eloc[mi];
        Ss[(m0 + mi) * 16 + tx] = saloc[mi];
    }
    __syncthreads();
    if (tid < 64) {
        float se = 0.0f, ss = 0.0f;
        #pragma unroll
        for (int x = 0; x < 16; x++) { se += Es[tid * 16 + x]; ss += Ss[tid * 16 + x]; }
        g_Ep[blockIdx.x * NM + tid] = se;
        g_sa[blockIdx.x * NM + tid] = ss;
    }
}

// ---------------- GEMM2 (pipelined, K-split x54): F2 = -((q a) @ xst + b @ Jx) ----------------
__global__ __launch_bounds__(256)
void gemm2_kernel(const float* __restrict__ xt, const float* __restrict__ jx) {
    __shared__ float Aa[2][16 * 128];
    __shared__ float Ab[2][16 * 128];
    __shared__ float Bx[2][16 * 64];
    __shared__ float Bj[2][16 * 64];

    const int tid = threadIdx.x;
    const int tx = tid & 15;
    const int ty = tid >> 4;
    const int p0 = blockIdx.x * 64;
    const int t0 = blockIdx.y * G2_CHUNK;

    const int lam = tid >> 2, lac = tid & 3;
    const int lbk = tid >> 4, lbc = tid & 15;

    u64 acc[4][2];
    #pragma unroll
    for (int i = 0; i < 4; i++) { acc[i][0] = 0ull; acc[i][1] = 0ull; }

    float4 av, bv, xv, jv;

    auto ldg_tile = [&](int kt) {
        int tt0 = t0 + kt * 16;
        int ta = tt0 + 4 * lac;
        av = make_float4(0.f, 0.f, 0.f, 0.f);
        bv = make_float4(0.f, 0.f, 0.f, 0.f);
        if (ta < NT) {
            av = *(const float4*)&g_a[lam * NTPAD + ta];
            bv = *(const float4*)&g_b[lam * NTPAD + ta];
        }
        int tg = tt0 + lbk;
        int pc = p0 + 4 * lbc;
        xv = make_float4(0.f, 0.f, 0.f, 0.f);
        jv = make_float4(0.f, 0.f, 0.f, 0.f);
        if (tg < NT && pc < NP) {
            xv = *(const float4*)&xt[(size_t)tg * NP + pc];
            jv = *(const float4*)&jx[(size_t)tg * NP + pc];
        }
    };
    auto sts_tile = [&](int buf) {
        #pragma unroll
        for (int i = 0; i < 4; i++) {
            float va = (i == 0) ? av.x : (i == 1) ? av.y : (i == 2) ? av.z : av.w;
            float vb = (i == 0) ? bv.x : (i == 1) ? bv.y : (i == 2) ? bv.z : bv.w;
            *(float2*)&Aa[buf][(4 * lac + i) * 128 + 2 * lam] = make_float2(va, va);
            *(float2*)&Ab[buf][(4 * lac + i) * 128 + 2 * lam] = make_float2(vb, vb);
        }
        *(float4*)&Bx[buf][lbk * 64 + 4 * lbc] = xv;
        *(float4*)&Bj[buf][lbk * 64 + 4 * lbc] = jv;
    };

    ldg_tile(0);
    sts_tile(0);
    ldg_tile(1);
    __syncthreads();

    for (int kt = 0; kt < G2_NKT; kt++) {
        const int cur = kt & 1;
        if (kt + 1 < G2_NKT) {
            sts_tile(cur ^ 1);
            if (kt + 2 < G2_NKT) ldg_tile(kt + 2);
        }
        #pragma unroll
        for (int k = 0; k < 16; k++) {
            ulonglong2 Aa01 = *(const ulonglong2*)&Aa[cur][k * 128 + 8 * ty];
            ulonglong2 Aa23 = *(const ulonglong2*)&Aa[cur][k * 128 + 8 * ty + 4];
            ulonglong2 Ab01 = *(const ulonglong2*)&Ab[cur][k * 128 + 8 * ty];
            ulonglong2 Ab23 = *(const ulonglong2*)&Ab[cur][k * 128 + 8 * ty + 4];
            ulonglong2 X   = *(const ulonglong2*)&Bx[cur][k * 64 + 4 * tx];
            ulonglong2 J   = *(const ulonglong2*)&Bj[cur][k * 64 + 4 * tx];
            ffma2(acc[0][0], Aa01.x, X.x); ffma2(acc[0][1], Aa01.x, X.y);
            ffma2(acc[1][0], Aa01.y, X.x); ffma2(acc[1][1], Aa01.y, X.y);
            ffma2(acc[2][0], Aa23.x, X.x); ffma2(acc[2][1], Aa23.x, X.y);
            ffma2(acc[3][0], Aa23.y, X.x); ffma2(acc[3][1], Aa23.y, X.y);
            ffma2(acc[0][0], Ab01.x, J.x); ffma2(acc[0][1], Ab01.x, J.y);
            ffma2(acc[1][0], Ab01.y, J.x); ffma2(acc[1][1], Ab01.y, J.y);
            ffma2(acc[2][0], Ab23.x, J.x); ffma2(acc[2][1], Ab23.x, J.y);
            ffma2(acc[3][0], Ab23.y, J.x); ffma2(acc[3][1], Ab23.y, J.y);
        }
        __syncthreads();
    }

    #pragma unroll
    for (int mi = 0; mi < 4; mi++) {
        float2 u0 = upk(acc[mi][0]);
        float2 u1 = upk(acc[mi][1]);
        int m = ty * 4 + mi;
        *(float4*)&g_F2[((size_t)blockIdx.y * NM + m) * G2_PPAD + p0 + 4 * tx] =
            make_float4(-u0.x, -u0.y, -u1.x, -u1.y);
    }
}

// ---------------- final ----------------
__global__ void final_kernel(const float* __restrict__ Rs, float* __restrict__ out) {
    __shared__ float Fxs[NP];
    __shared__ float ssa;
    const int m = blockIdx.x;
    const int tid = threadIdx.x;

    if (tid < 32) {
        float s = 0.0f;
        for (int b = tid; b < G1_TT; b += 32) s += g_sa[b * NM + m];
        #pragma unroll
        for (int o = 16; o > 0; o >>= 1) s += __shfl_xor_sync(0xffffffffu, s, o);
        if (tid == 0) ssa = s;
    } else if (tid < 64) {
        int l = tid - 32;
        float e = 0.0f;
        for (int b = l; b < G1_TT; b += 32) e += g_Ep[b * NM + m];
        #pragma unroll
        for (int o = 16; o > 0; o >>= 1) e += __shfl_xor_sync(0xffffffffu, e, o);
        if (l == 0) out[m] = e / QV;
    }
    __syncthreads();

    if (tid < NP) {
        float F = ssa * g_qxs[m * NP + tid];
        #pragma unroll 6
        for (int ks = 0; ks < G2_KS; ks++)
            F += g_F2[((size_t)ks * NM + m) * G2_PPAD + tid];
        Fxs[tid] = F * g_xs3[m * NP + tid];
    }
    __syncthreads();

    if (tid < NA * 3) {
        int a = tid / 3, c = tid % 3;
        float Ra = Rs[(m * NA + a) * 3 + c];
        float acc = 0.0f;
        #pragma unroll
        for (int bb = 0; bb < NA; bb++) {
            if (bb == a) continue;
            int hi = (a > bb) ? a : bb;
            int lo = (a > bb) ? bb : a;
            int p = hi * (hi - 1) / 2 + lo;
            float Rb = Rs[(m * NA + bb) * 3 + c];
            acc += (Rb - Ra) * Fxs[p];
        }
        out[NM + m * NA * 3 + tid] = acc;
    }
}

extern "C" void kernel_launch(void* const* d_in, const int* in_sizes, int n_in,
                              void* d_out, int out_size) {
    const float* Rs = (const float*)d_in[0];
    const float* xs_train = (const float*)d_in[1];
    const float* Jx = (const float*)d_in[2];
    float* out = (float*)d_out;

    prep_kernel<<<NM + NTPAD / 8, 256>>>(Rs, xs_train, Jx);
    gemm1p_kernel<<<dim3(G1_TT, G1_KS), 256>>>(xs_train, Jx);
    ep_kernel<<<G1_TT, 256>>>();
    gemm2_kernel<<<dim3(G2_PT, G2_KS), 256>>>(xs_train, Jx);
    final_kernel<<<NM, 288>>>(Rs, out);
}